// round 12
// baseline (speedup 1.0000x reference)
#include <cuda_runtime.h>
#include <cuda_fp16.h>
#include <math_constants.h>
#include <cstdint>

// Problem constants
#define B_  2
#define S_  2048
#define H_  1024
#define NH_ 16
#define HD_ 64
#define MROWS_ (B_ * S_)          // 4096
#define LN_ROWS_ (B_ * S_ * NH_)  // 65536

// Scratch (device globals — allocation-free rule)
__device__ __half g_qkvh[(size_t)MROWS_ * 3 * H_];  // [4096, 3072] fp16
__device__ __half g_hsh[(size_t)MROWS_ * H_];       // hs in fp16
__device__ __half g_wah[(size_t)H_ * 3 * H_];       // W_attn fp16
__device__ __half g_wph[(size_t)H_ * H_];           // W_proj fp16
__device__ __half g_qh [(size_t)MROWS_ * H_];       // [B*NH, S, HD] fp16
__device__ __half g_kh [(size_t)MROWS_ * H_];
__device__ __half g_vh [(size_t)MROWS_ * H_];
__device__ __half g_ctxh[(size_t)MROWS_ * H_];      // [B, S, H] fp16

// ---------------------------------------------------------------------------
// helpers
// ---------------------------------------------------------------------------
__device__ __forceinline__ uint32_t h2r(float lo, float hi) {
    __half2 h = __floats2half2_rn(lo, hi);
    return *reinterpret_cast<uint32_t*>(&h);
}

__device__ __forceinline__ void mma_fp16(float c[4], const uint32_t a[4],
                                         const uint32_t b[2]) {
    asm volatile(
        "mma.sync.aligned.m16n8k16.row.col.f32.f16.f16.f32 "
        "{%0,%1,%2,%3}, {%4,%5,%6,%7}, {%8,%9}, {%0,%1,%2,%3};"
        : "+f"(c[0]), "+f"(c[1]), "+f"(c[2]), "+f"(c[3])
        : "r"(a[0]), "r"(a[1]), "r"(a[2]), "r"(a[3]), "r"(b[0]), "r"(b[1]));
}

__device__ __forceinline__ void ldsm_x4(uint32_t r[4], uint32_t addr) {
    asm volatile("ldmatrix.sync.aligned.m8n8.x4.shared.b16 {%0,%1,%2,%3}, [%4];"
                 : "=r"(r[0]), "=r"(r[1]), "=r"(r[2]), "=r"(r[3]) : "r"(addr));
}

__device__ __forceinline__ void ldsm_x4_t(uint32_t r[4], uint32_t addr) {
    asm volatile("ldmatrix.sync.aligned.m8n8.x4.trans.shared.b16 {%0,%1,%2,%3}, [%4];"
                 : "=r"(r[0]), "=r"(r[1]), "=r"(r[2]), "=r"(r[3]) : "r"(addr));
}

__device__ __forceinline__ void cp16(uint32_t smem, const void* gmem) {
    asm volatile("cp.async.cg.shared.global [%0], [%1], 16;" ::
                 "r"(smem), "l"(gmem));
}
__device__ __forceinline__ void cp_commit() {
    asm volatile("cp.async.commit_group;");
}
template <int N>
__device__ __forceinline__ void cp_wait() {
    asm volatile("cp.async.wait_group %0;" :: "n"(N));
}

// ---------------------------------------------------------------------------
// fp32 -> fp16 conversion (vectorized, n % 4 == 0)
// ---------------------------------------------------------------------------
__global__ __launch_bounds__(256) void f2h(const float4* __restrict__ in,
                                           uint2* __restrict__ out, int n4)
{
    int i = blockIdx.x * blockDim.x + threadIdx.x;
    if (i < n4) {
        float4 v = in[i];
        uint2 o;
        o.x = h2r(v.x, v.y);
        o.y = h2r(v.z, v.w);
        out[i] = o;
    }
}

// ---------------------------------------------------------------------------
// FP16 tensor-core GEMM, 6-stage cp.async ring, 2 k-tiles (BK=16 each) per
// loop iteration -> HALF the barriers of R10. Dynamic smem (61.5 KB).
//   As[m][k]  stride 24 halfs (48B)  -> ldsm + stores conflict-free
//   Bs[k][n]  stride 136 halfs (272B) -> x4 trans-ldsm conflict-free
// ---------------------------------------------------------------------------
#define AH 24
#define BH 136
#define NSTG 6
#define GEMM_SMEM_BYTES (NSTG * (128 * AH + 16 * BH) * 2)

template <typename OutT>
__global__ __launch_bounds__(256, 2) void gemm_fp16p(
    const __half* __restrict__ A, const __half* __restrict__ Bm,
    const float* __restrict__ bias, OutT* __restrict__ C,
    int M, int N, int K)
{
    extern __shared__ __half sm[];
    __half* AsBase = sm;                           // [NSTG][128][AH]
    __half* BsBase = sm + (size_t)NSTG * 128 * AH; // [NSTG][16][BH]

    const int tid  = threadIdx.x;
    const int lane = tid & 31;
    const int warp = tid >> 5;
    const int wm = (warp & 1) * 64;
    const int wn = (warp >> 1) * 32;
    const int gid = lane >> 2;
    const int tig = lane & 3;
    const int brow = blockIdx.y * 128;
    const int bcol = blockIdx.x * 128;

    // A tile 128x16 halfs (4KB): row = tid>>1, col halfs = (tid&1)*8
    const int aRow = tid >> 1;
    const int aCol = (tid & 1) * 8;
    const __half* Aptr = A + (size_t)(brow + aRow) * K + aCol;

    // B tile 16x128 halfs (4KB): row = tid>>4, col halfs = (tid&15)*8
    const int bRow = tid >> 4;
    const int bCol = (tid & 15) * 8;
    const __half* Bptr = Bm + (size_t)bRow * N + bcol + bCol;

    const uint32_t asB = (uint32_t)__cvta_generic_to_shared(AsBase);
    const uint32_t bsB = (uint32_t)__cvta_generic_to_shared(BsBase);
    const uint32_t ABUF = 128 * AH * 2;
    const uint32_t BBUF = 16 * BH * 2;
    const uint32_t aSt = (uint32_t)(aRow * AH + aCol) * 2;
    const uint32_t bSt = (uint32_t)(bRow * BH + bCol) * 2;

    float c[4][4][4];
#pragma unroll
    for (int i = 0; i < 4; i++)
#pragma unroll
        for (int j = 0; j < 4; j++)
#pragma unroll
            for (int r = 0; r < 4; r++) c[i][j][r] = 0.f;

    // ldsm per-thread coords
    const int l8  = lane & 7;
    const int h8  = (lane >> 3) & 1;
    const int h16 = (lane >> 4) & 1;
    const uint32_t aOff = ((uint32_t)(wm + l8 + h8 * 8) * AH + h16 * 8) * 2;
    const uint32_t bOff = ((uint32_t)(l8 + h8 * 8) * BH + wn + h16 * 8) * 2;

    const int ntiles = K / 16;        // 64
    const int niters = ntiles / 2;    // 32

    // prologue: issue tiles 0..3 (one group per tile)
#pragma unroll
    for (int s = 0; s < 4; s++) {
        cp16(asB + (uint32_t)s * ABUF + aSt, Aptr + s * 16);
        cp16(bsB + (uint32_t)s * BBUF + bSt, Bptr + (size_t)(s * 16) * N);
        cp_commit();
    }

    int bufR = 0;   // buffer of tile 2j
    int bufW = 4;   // buffer of tile 2j+4
    for (int j = 0; j < niters; j++) {
        cp_wait<2>();        // groups for tiles <= 2j+1 retired
        __syncthreads();     // visible to all; prior reads of reused bufs done

        // issue tiles 2j+4, 2j+5 (empty-commit in the tail)
#pragma unroll
        for (int e = 0; e < 2; e++) {
            const int tt = 2 * j + 4 + e;
            if (tt < ntiles) {
                const uint32_t st = (uint32_t)((bufW + e >= NSTG) ? bufW + e - NSTG
                                                                 : bufW + e);
                cp16(asB + st * ABUF + aSt, Aptr + tt * 16);
                cp16(bsB + st * BBUF + bSt, Bptr + (size_t)(tt * 16) * N);
            }
            cp_commit();
        }

        // compute tiles 2j, 2j+1
#pragma unroll
        for (int e = 0; e < 2; e++) {
            const uint32_t buf = (uint32_t)((bufR + e >= NSTG) ? bufR + e - NSTG
                                                               : bufR + e);
            const uint32_t aBase = asB + buf * ABUF + aOff;
            const uint32_t bBase = bsB + buf * BBUF + bOff;
            uint32_t af[4][4], bfr[2][4];
#pragma unroll
            for (int mt = 0; mt < 4; mt++)
                ldsm_x4(af[mt], aBase + (uint32_t)(mt * 16 * AH) * 2);
#pragma unroll
            for (int np = 0; np < 2; np++)
                ldsm_x4_t(bfr[np], bBase + (uint32_t)(np * 16) * 2);
#pragma unroll
            for (int mt = 0; mt < 4; mt++)
#pragma unroll
                for (int np = 0; np < 2; np++) {
                    mma_fp16(c[mt][2 * np],     af[mt], &bfr[np][0]);
                    mma_fp16(c[mt][2 * np + 1], af[mt], &bfr[np][2]);
                }
        }

        bufR += 2; if (bufR >= NSTG) bufR -= NSTG;
        bufW += 2; if (bufW >= NSTG) bufW -= NSTG;
    }

    // epilogue: bias add + store (fp32 or fp16)
#pragma unroll
    for (int mt = 0; mt < 4; mt++) {
        const int row = brow + wm + mt * 16 + gid;
#pragma unroll
        for (int nt = 0; nt < 4; nt++) {
            const int col = bcol + wn + nt * 8 + tig * 2;
            const float b0 = bias[col], b1 = bias[col + 1];
            float v00 = c[mt][nt][0] + b0, v01 = c[mt][nt][1] + b1;
            float v10 = c[mt][nt][2] + b0, v11 = c[mt][nt][3] + b1;
            if (sizeof(OutT) == 4) {
                *(float2*)&((float*)C)[(size_t)row * N + col] = make_float2(v00, v01);
                *(float2*)&((float*)C)[(size_t)(row + 8) * N + col] = make_float2(v10, v11);
            } else {
                *(__half2*)&((__half*)C)[(size_t)row * N + col] = __floats2half2_rn(v00, v01);
                *(__half2*)&((__half*)C)[(size_t)(row + 8) * N + col] = __floats2half2_rn(v10, v11);
            }
        }
    }
}

// ---------------------------------------------------------------------------
// Split QKV (fp16) + per-head LayerNorm on Q,K; copy V. fp16 head-major out.
// 8 lanes per row; 3-shuffle octet reduction.
// ---------------------------------------------------------------------------
__global__ __launch_bounds__(256) void qkv_split_ln8(
    const __half* __restrict__ qkv,
    const float* __restrict__ qg, const float* __restrict__ qb,
    const float* __restrict__ kg, const float* __restrict__ kb,
    __half* __restrict__ qh, __half* __restrict__ kh, __half* __restrict__ vh)
{
    const int oct = (blockIdx.x * blockDim.x + threadIdx.x) >> 3;  // row id
    const int l8  = threadIdx.x & 7;
    int t = oct / LN_ROWS_;      // 0:q 1:k 2:v
    int row = oct - t * LN_ROWS_;
    if (t >= 3) return;

    int b = row / (S_ * NH_);
    int rem = row - b * (S_ * NH_);
    int s = rem / NH_;
    int n = rem - s * NH_;

    const __half* src = qkv + (size_t)(b * S_ + s) * (3 * H_) + t * H_ + n * HD_ + l8 * 8;
    __half* dst = (t == 0 ? qh : (t == 1 ? kh : vh)) +
                  ((size_t)(b * NH_ + n) * S_ + s) * HD_ + l8 * 8;

    uint4 v = *(const uint4*)src;
    if (t == 2) { *(uint4*)dst = v; return; }

    __half2 hv[4];
    *(uint4*)hv = v;
    float x[8];
#pragma unroll
    for (int i = 0; i < 4; i++) {
        float2 f = __half22float2(hv[i]);
        x[2 * i] = f.x; x[2 * i + 1] = f.y;
    }

    float s1 = 0.f, s2 = 0.f;
#pragma unroll
    for (int i = 0; i < 8; i++) { s1 += x[i]; s2 += x[i] * x[i]; }
#pragma unroll
    for (int o = 1; o < 8; o <<= 1) {
        s1 += __shfl_xor_sync(0xffffffffu, s1, o);
        s2 += __shfl_xor_sync(0xffffffffu, s2, o);
    }
    float mu  = s1 * (1.0f / HD_);
    float var = s2 * (1.0f / HD_) - mu * mu;
    float inv = rsqrtf(var + 1e-5f);

    const float* g  = (t == 0) ? qg : kg;
    const float* be = (t == 0) ? qb : kb;
    float4 g0 = *(const float4*)&g[l8 * 8];
    float4 g1 = *(const float4*)&g[l8 * 8 + 4];
    float4 b0 = *(const float4*)&be[l8 * 8];
    float4 b1 = *(const float4*)&be[l8 * 8 + 4];

    __half2 oh[4];
    oh[0] = __floats2half2_rn((x[0] - mu) * inv * g0.x + b0.x,
                              (x[1] - mu) * inv * g0.y + b0.y);
    oh[1] = __floats2half2_rn((x[2] - mu) * inv * g0.z + b0.z,
                              (x[3] - mu) * inv * g0.w + b0.w);
    oh[2] = __floats2half2_rn((x[4] - mu) * inv * g1.x + b1.x,
                              (x[5] - mu) * inv * g1.y + b1.y);
    oh[3] = __floats2half2_rn((x[6] - mu) * inv * g1.z + b1.z,
                              (x[7] - mu) * inv * g1.w + b1.w);
    *(uint4*)dst = *(uint4*)oh;
}

// ---------------------------------------------------------------------------
// Causal flash attention, fp16 tensor cores. ctx written as fp16.
// ---------------------------------------------------------------------------
#define QST 72
#define KST 72
#define VST 72

__global__ __launch_bounds__(256, 2) void flash_attn_fp16(
    const __half* __restrict__ qh, const __half* __restrict__ kh,
    const __half* __restrict__ vh, __half* __restrict__ ctx)
{
    __shared__ __half Qs[128][QST];
    __shared__ __half Ks[32][KST];
    __shared__ __half Vs[32][VST];

    const int bh  = blockIdx.y;
    const int qt  = blockIdx.x;
    const int tid = threadIdx.x;
    const int lane = tid & 31;
    const int w    = tid >> 5;
    const int gid  = lane >> 2;
    const int tig  = lane & 3;
    const int l8   = lane & 7;
    const int h8   = (lane >> 3) & 1;
    const int h16  = (lane >> 4) & 1;
    const int qbase = qt * 128;
    const int wrow  = w * 16;

    const __half* Q  = qh + (size_t)bh * S_ * HD_ + (size_t)qbase * HD_;
    const __half* Kp = kh + (size_t)bh * S_ * HD_;
    const __half* Vp = vh + (size_t)bh * S_ * HD_;

    for (int i = tid; i < 128 * 8; i += 256) {
        int r = i >> 3, c8 = (i & 7) * 8;
        *(uint4*)&Qs[r][c8] = *(const uint4*)&Q[r * HD_ + c8];
    }
    __syncthreads();

    const uint32_t qsB = (uint32_t)__cvta_generic_to_shared(&Qs[0][0]) +
                         ((uint32_t)(wrow + l8 + h8 * 8) * QST + h16 * 8) * 2;
    uint32_t qa[4][4];
#pragma unroll
    for (int ks = 0; ks < 4; ks++)
        ldsm_x4(qa[ks], qsB + (uint32_t)(ks * 16) * 2);
    __syncthreads();

    const uint32_t ksB = (uint32_t)__cvta_generic_to_shared(&Ks[0][0]) +
                         ((uint32_t)(l8 + h16 * 8) * KST + h8 * 8) * 2;
    const uint32_t vsB = (uint32_t)__cvta_generic_to_shared(&Vs[0][0]) +
                         ((uint32_t)(l8 + h8 * 8) * VST + h16 * 8) * 2;

    float o[8][4];
#pragma unroll
    for (int i = 0; i < 8; i++)
#pragma unroll
        for (int j = 0; j < 4; j++) o[i][j] = 0.f;
    float m0 = -CUDART_INF_F, m1 = -CUDART_INF_F;
    float l0 = 0.f, l1 = 0.f;

    const int r0g = qbase + wrow + gid;
    const int r1g = r0g + 8;
    const int rmaxw = qbase + wrow + 15;
    const int nkt = (qt + 1) * 4;
    const float scl = 0.125f;

    for (int kt = 0; kt < nkt; kt++) {
        const int kbase = kt * 32;
        {
            int r = tid >> 3, c8 = (tid & 7) * 8;
            *(uint4*)&Ks[r][c8] = *(const uint4*)&Kp[(size_t)(kbase + r) * HD_ + c8];
            *(uint4*)&Vs[r][c8] = *(const uint4*)&Vp[(size_t)(kbase + r) * HD_ + c8];
        }
        __syncthreads();

        if (kbase <= rmaxw) {
            float s[4][4];
#pragma unroll
            for (int nt = 0; nt < 4; nt++)
#pragma unroll
                for (int j = 0; j < 4; j++) s[nt][j] = 0.f;
#pragma unroll
            for (int np = 0; np < 2; np++) {
#pragma unroll
                for (int ks = 0; ks < 4; ks++) {
                    uint32_t b4[4];
                    ldsm_x4(b4, ksB + (uint32_t)(np * 16 * KST + ks * 16) * 2);
                    mma_fp16(s[2 * np],     qa[ks], &b4[0]);
                    mma_fp16(s[2 * np + 1], qa[ks], &b4[2]);
                }
            }

            if (kbase + 31 <= qbase + wrow) {
#pragma unroll
                for (int nt = 0; nt < 4; nt++)
#pragma unroll
                    for (int j = 0; j < 4; j++) s[nt][j] *= scl;
            } else {
#pragma unroll
                for (int nt = 0; nt < 4; nt++) {
                    int c0 = kbase + nt * 8 + tig * 2;
                    s[nt][0] = (c0     <= r0g) ? s[nt][0] * scl : -CUDART_INF_F;
                    s[nt][1] = (c0 + 1 <= r0g) ? s[nt][1] * scl : -CUDART_INF_F;
                    s[nt][2] = (c0     <= r1g) ? s[nt][2] * scl : -CUDART_INF_F;
                    s[nt][3] = (c0 + 1 <= r1g) ? s[nt][3] * scl : -CUDART_INF_F;
                }
            }

            float mt0 = fmaxf(fmaxf(s[0][0], s[0][1]), fmaxf(s[1][0], s[1][1]));
            mt0 = fmaxf(mt0, fmaxf(fmaxf(s[2][0], s[2][1]), fmaxf(s[3][0], s[3][1])));
            float mt1 = fmaxf(fmaxf(s[0][2], s[0][3]), fmaxf(s[1][2], s[1][3]));
            mt1 = fmaxf(mt1, fmaxf(fmaxf(s[2][2], s[2][3]), fmaxf(s[3][2], s[3][3])));
            mt0 = fmaxf(mt0, __shfl_xor_sync(0xffffffffu, mt0, 1));
            mt0 = fmaxf(mt0, __shfl_xor_sync(0xffffffffu, mt0, 2));
            mt1 = fmaxf(mt1, __shfl_xor_sync(0xffffffffu, mt1, 1));
            mt1 = fmaxf(mt1, __shfl_xor_sync(0xffffffffu, mt1, 2));

            float mn0 = fmaxf(m0, mt0), mn1 = fmaxf(m1, mt1);
            float a0 = __expf(m0 - mn0), a1 = __expf(m1 - mn1);
            m0 = mn0; m1 = mn1;

            float p[4][4];
            float ps0 = 0.f, ps1 = 0.f;
#pragma unroll
            for (int nt = 0; nt < 4; nt++) {
                p[nt][0] = __expf(s[nt][0] - mn0);
                p[nt][1] = __expf(s[nt][1] - mn0);
                p[nt][2] = __expf(s[nt][2] - mn1);
                p[nt][3] = __expf(s[nt][3] - mn1);
                ps0 += p[nt][0] + p[nt][1];
                ps1 += p[nt][2] + p[nt][3];
            }
            ps0 += __shfl_xor_sync(0xffffffffu, ps0, 1);
            ps0 += __shfl_xor_sync(0xffffffffu, ps0, 2);
            ps1 += __shfl_xor_sync(0xffffffffu, ps1, 1);
            ps1 += __shfl_xor_sync(0xffffffffu, ps1, 2);
            l0 = l0 * a0 + ps0;
            l1 = l1 * a1 + ps1;

            uint32_t pa[2][4];
#pragma unroll
            for (int ks = 0; ks < 2; ks++) {
                pa[ks][0] = h2r(p[2 * ks][0],     p[2 * ks][1]);
                pa[ks][1] = h2r(p[2 * ks][2],     p[2 * ks][3]);
                pa[ks][2] = h2r(p[2 * ks + 1][0], p[2 * ks + 1][1]);
                pa[ks][3] = h2r(p[2 * ks + 1][2], p[2 * ks + 1][3]);
            }

#pragma unroll
            for (int nt = 0; nt < 8; nt++) {
                o[nt][0] *= a0; o[nt][1] *= a0;
                o[nt][2] *= a1; o[nt][3] *= a1;
            }
#pragma unroll
            for (int np = 0; np < 4; np++) {
#pragma unroll
                for (int ks = 0; ks < 2; ks++) {
                    uint32_t b4[4];
                    ldsm_x4_t(b4, vsB + (uint32_t)(ks * 16 * VST + np * 16) * 2);
                    mma_fp16(o[2 * np],     pa[ks], &b4[0]);
                    mma_fp16(o[2 * np + 1], pa[ks], &b4[2]);
                }
            }
        }
        __syncthreads();
    }

    const int bb = bh >> 4;
    const int nh = bh & 15;
    const float inv0 = 1.0f / l0;
    const float inv1 = 1.0f / l1;
    __half* orow0 = ctx + (size_t)(bb * S_ + r0g) * H_ + nh * HD_;
    __half* orow1 = ctx + (size_t)(bb * S_ + r1g) * H_ + nh * HD_;
#pragma unroll
    for (int nt = 0; nt < 8; nt++) {
        int col = nt * 8 + tig * 2;
        *(__half2*)&orow0[col] = __floats2half2_rn(o[nt][0] * inv0, o[nt][1] * inv0);
        *(__half2*)&orow1[col] = __floats2half2_rn(o[nt][2] * inv1, o[nt][3] * inv1);
    }
}

// ---------------------------------------------------------------------------
extern "C" void kernel_launch(void* const* d_in, const int* in_sizes, int n_in,
                              void* d_out, int out_size)
{
    const float* hs = (const float*)d_in[0];
    const float* Wa = (const float*)d_in[1];
    const float* ba = (const float*)d_in[2];
    const float* Wp = (const float*)d_in[3];
    const float* bp = (const float*)d_in[4];
    const float* qg = (const float*)d_in[5];
    const float* qb = (const float*)d_in[6];
    const float* kg = (const float*)d_in[7];
    const float* kb = (const float*)d_in[8];
    float* out = (float*)d_out;

    __half *qkvh, *hsh, *wah, *wph, *qh, *kh, *vh, *ctxh;
    cudaGetSymbolAddress((void**)&qkvh, g_qkvh);
    cudaGetSymbolAddress((void**)&hsh, g_hsh);
    cudaGetSymbolAddress((void**)&wah, g_wah);
    cudaGetSymbolAddress((void**)&wph, g_wph);
    cudaGetSymbolAddress((void**)&qh,  g_qh);
    cudaGetSymbolAddress((void**)&kh,  g_kh);
    cudaGetSymbolAddress((void**)&vh,  g_vh);
    cudaGetSymbolAddress((void**)&ctxh, g_ctxh);

    // raise dynamic smem limit for the GEMM (host attribute call; idempotent)
    cudaFuncSetAttribute(gemm_fp16p<__half>,
                         cudaFuncAttributeMaxDynamicSharedMemorySize,
                         GEMM_SMEM_BYTES);
    cudaFuncSetAttribute(gemm_fp16p<float>,
                         cudaFuncAttributeMaxDynamicSharedMemorySize,
                         GEMM_SMEM_BYTES);

    // 0) fp32 -> fp16 input conversions
    {
        int n4;
        n4 = (MROWS_ * H_) / 4;
        f2h<<<(n4 + 255) / 256, 256>>>((const float4*)hs, (uint2*)hsh, n4);
        n4 = (H_ * 3 * H_) / 4;
        f2h<<<(n4 + 255) / 256, 256>>>((const float4*)Wa, (uint2*)wah, n4);
        n4 = (H_ * H_) / 4;
        f2h<<<(n4 + 255) / 256, 256>>>((const float4*)Wp, (uint2*)wph, n4);
    }

    // 1) QKV GEMM (fp16 out): [4096,1024] @ [1024,3072] + bias
    gemm_fp16p<__half><<<dim3(3 * H_ / 128, MROWS_ / 128), 256,
                         GEMM_SMEM_BYTES>>>(hsh, wah, ba, qkvh,
                                            MROWS_, 3 * H_, H_);

    // 2) split + QK layernorm + V copy (8 lanes/row)
    {
        int threads_total = 3 * LN_ROWS_ * 8;
        qkv_split_ln8<<<threads_total / 256, 256>>>(qkvh, qg, qb, kg, kb, qh, kh, vh);
    }

    // 3) causal flash attention (fp16; ctx fp16)
    flash_attn_fp16<<<dim3(S_ / 128, B_ * NH_), 256>>>(qh, kh, vh, ctxh);

    // 4) output projection (fp32 out): [4096,1024] @ [1024,1024] + bias
    gemm_fp16p<float><<<dim3(H_ / 128, MROWS_ / 128), 256,
                        GEMM_SMEM_BYTES>>>(ctxh, wph, bp, out,
                                           MROWS_, H_, H_);
}

// round 13
// speedup vs baseline: 1.1520x; 1.1520x over previous
#include <cuda_runtime.h>
#include <cuda_fp16.h>
#include <math_constants.h>
#include <cstdint>

// Problem constants
#define B_  2
#define S_  2048
#define H_  1024
#define NH_ 16
#define HD_ 64
#define MROWS_ (B_ * S_)          // 4096
#define LN_ROWS_ (B_ * S_ * NH_)  // 65536

// Scratch (device globals — allocation-free rule)
__device__ __half g_qkvh[(size_t)MROWS_ * 3 * H_];  // [4096, 3072] fp16
__device__ __half g_hsh[(size_t)MROWS_ * H_];       // hs in fp16
__device__ __half g_wah[(size_t)H_ * 3 * H_];       // W_attn fp16
__device__ __half g_wph[(size_t)H_ * H_];           // W_proj fp16
__device__ __half g_qh [(size_t)MROWS_ * H_];       // [B*NH, S, HD] fp16
__device__ __half g_kh [(size_t)MROWS_ * H_];
__device__ __half g_vh [(size_t)MROWS_ * H_];
__device__ __half g_ctxh[(size_t)MROWS_ * H_];      // [B, S, H] fp16

// ---------------------------------------------------------------------------
// helpers
// ---------------------------------------------------------------------------
__device__ __forceinline__ uint32_t h2r(float lo, float hi) {
    __half2 h = __floats2half2_rn(lo, hi);
    return *reinterpret_cast<uint32_t*>(&h);
}

__device__ __forceinline__ void mma_fp16(float c[4], const uint32_t a[4],
                                         const uint32_t b[2]) {
    asm volatile(
        "mma.sync.aligned.m16n8k16.row.col.f32.f16.f16.f32 "
        "{%0,%1,%2,%3}, {%4,%5,%6,%7}, {%8,%9}, {%0,%1,%2,%3};"
        : "+f"(c[0]), "+f"(c[1]), "+f"(c[2]), "+f"(c[3])
        : "r"(a[0]), "r"(a[1]), "r"(a[2]), "r"(a[3]), "r"(b[0]), "r"(b[1]));
}

__device__ __forceinline__ void ldsm_x4(uint32_t r[4], uint32_t addr) {
    asm volatile("ldmatrix.sync.aligned.m8n8.x4.shared.b16 {%0,%1,%2,%3}, [%4];"
                 : "=r"(r[0]), "=r"(r[1]), "=r"(r[2]), "=r"(r[3]) : "r"(addr));
}

__device__ __forceinline__ void ldsm_x4_t(uint32_t r[4], uint32_t addr) {
    asm volatile("ldmatrix.sync.aligned.m8n8.x4.trans.shared.b16 {%0,%1,%2,%3}, [%4];"
                 : "=r"(r[0]), "=r"(r[1]), "=r"(r[2]), "=r"(r[3]) : "r"(addr));
}

__device__ __forceinline__ void cp16(uint32_t smem, const void* gmem) {
    asm volatile("cp.async.cg.shared.global [%0], [%1], 16;" ::
                 "r"(smem), "l"(gmem));
}
__device__ __forceinline__ void cp_commit() {
    asm volatile("cp.async.commit_group;");
}
template <int N>
__device__ __forceinline__ void cp_wait() {
    asm volatile("cp.async.wait_group %0;" :: "n"(N));
}

// ---------------------------------------------------------------------------
// fp32 -> fp16 conversion, all three inputs in ONE launch (segment dispatch)
// seg0: hs (MROWS_*H_), seg1: W_attn (H_*3H_), seg2: W_proj (H_*H_)
// ---------------------------------------------------------------------------
#define N4_HS ((MROWS_ * H_) / 4)
#define N4_WA ((H_ * 3 * H_) / 4)
#define N4_WP ((H_ * H_) / 4)

__global__ __launch_bounds__(256) void f2h_all(
    const float4* __restrict__ hs, const float4* __restrict__ wa,
    const float4* __restrict__ wp,
    uint2* __restrict__ hsh, uint2* __restrict__ wah, uint2* __restrict__ wph)
{
    int i = blockIdx.x * blockDim.x + threadIdx.x;
    const float4* in;
    uint2* out;
    if (i < N4_HS) {
        in = hs; out = hsh;
    } else if (i < N4_HS + N4_WA) {
        i -= N4_HS; in = wa; out = wah;
    } else if (i < N4_HS + N4_WA + N4_WP) {
        i -= N4_HS + N4_WA; in = wp; out = wph;
    } else return;
    float4 v = in[i];
    uint2 o;
    o.x = h2r(v.x, v.y);
    o.y = h2r(v.z, v.w);
    out[i] = o;
}

// ---------------------------------------------------------------------------
// FP16 tensor-core GEMM, 4-stage cp.async pipeline, BK=16  (R10 config).
//   As[m][k]  stride 24 halfs (48B)  -> ldsm + stores conflict-free
//   Bs[k][n]  stride 136 halfs (272B) -> x4 trans-ldsm conflict-free
// ---------------------------------------------------------------------------
#define AH 24
#define BH 136
#define STAGES 4

template <typename OutT>
__global__ __launch_bounds__(256, 2) void gemm_fp16p(
    const __half* __restrict__ A, const __half* __restrict__ Bm,
    const float* __restrict__ bias, OutT* __restrict__ C,
    int M, int N, int K)
{
    __shared__ __half As[STAGES][128][AH];
    __shared__ __half Bs[STAGES][16][BH];

    const int tid  = threadIdx.x;
    const int lane = tid & 31;
    const int warp = tid >> 5;
    const int wm = (warp & 1) * 64;
    const int wn = (warp >> 1) * 32;
    const int gid = lane >> 2;
    const int tig = lane & 3;
    const int brow = blockIdx.y * 128;
    const int bcol = blockIdx.x * 128;

    const int aRow = tid >> 1;
    const int aCol = (tid & 1) * 8;
    const __half* Aptr = A + (size_t)(brow + aRow) * K + aCol;

    const int bRow = tid >> 4;
    const int bCol = (tid & 15) * 8;
    const __half* Bptr = Bm + (size_t)bRow * N + bcol + bCol;

    const uint32_t asB = (uint32_t)__cvta_generic_to_shared(&As[0][0][0]);
    const uint32_t bsB = (uint32_t)__cvta_generic_to_shared(&Bs[0][0][0]);
    const uint32_t ABUF = 128 * AH * 2;
    const uint32_t BBUF = 16 * BH * 2;
    const uint32_t aSt = (uint32_t)(aRow * AH + aCol) * 2;
    const uint32_t bSt = (uint32_t)(bRow * BH + bCol) * 2;

    float c[4][4][4];
#pragma unroll
    for (int i = 0; i < 4; i++)
#pragma unroll
        for (int j = 0; j < 4; j++)
#pragma unroll
            for (int r = 0; r < 4; r++) c[i][j][r] = 0.f;

    const int l8  = lane & 7;
    const int h8  = (lane >> 3) & 1;
    const int h16 = (lane >> 4) & 1;
    const uint32_t aOff = ((uint32_t)(wm + l8 + h8 * 8) * AH + h16 * 8) * 2;
    const uint32_t bOff = ((uint32_t)(l8 + h8 * 8) * BH + wn + h16 * 8) * 2;

    const int iters = K / 16;   // 64

#pragma unroll
    for (int s = 0; s < STAGES - 1; s++) {
        cp16(asB + (uint32_t)s * ABUF + aSt, Aptr + s * 16);
        cp16(bsB + (uint32_t)s * BBUF + bSt, Bptr + (size_t)(s * 16) * N);
        cp_commit();
    }

    for (int t = 0; t < iters; t++) {
        cp_wait<STAGES - 2>();
        __syncthreads();

        if (t + STAGES - 1 < iters) {
            const int k0 = (t + STAGES - 1) * 16;
            const uint32_t st = (uint32_t)((t + STAGES - 1) & (STAGES - 1));
            cp16(asB + st * ABUF + aSt, Aptr + k0);
            cp16(bsB + st * BBUF + bSt, Bptr + (size_t)k0 * N);
        }
        cp_commit();

        const uint32_t buf = (uint32_t)(t & (STAGES - 1));
        const uint32_t aBase = asB + buf * ABUF + aOff;
        const uint32_t bBase = bsB + buf * BBUF + bOff;
        uint32_t af[4][4], bfr[2][4];
#pragma unroll
        for (int mt = 0; mt < 4; mt++)
            ldsm_x4(af[mt], aBase + (uint32_t)(mt * 16 * AH) * 2);
#pragma unroll
        for (int np = 0; np < 2; np++)
            ldsm_x4_t(bfr[np], bBase + (uint32_t)(np * 16) * 2);
#pragma unroll
        for (int mt = 0; mt < 4; mt++)
#pragma unroll
            for (int np = 0; np < 2; np++) {
                mma_fp16(c[mt][2 * np],     af[mt], &bfr[np][0]);
                mma_fp16(c[mt][2 * np + 1], af[mt], &bfr[np][2]);
            }
    }

#pragma unroll
    for (int mt = 0; mt < 4; mt++) {
        const int row = brow + wm + mt * 16 + gid;
#pragma unroll
        for (int nt = 0; nt < 4; nt++) {
            const int col = bcol + wn + nt * 8 + tig * 2;
            const float b0 = bias[col], b1 = bias[col + 1];
            float v00 = c[mt][nt][0] + b0, v01 = c[mt][nt][1] + b1;
            float v10 = c[mt][nt][2] + b0, v11 = c[mt][nt][3] + b1;
            if (sizeof(OutT) == 4) {
                *(float2*)&((float*)C)[(size_t)row * N + col] = make_float2(v00, v01);
                *(float2*)&((float*)C)[(size_t)(row + 8) * N + col] = make_float2(v10, v11);
            } else {
                *(__half2*)&((__half*)C)[(size_t)row * N + col] = __floats2half2_rn(v00, v01);
                *(__half2*)&((__half*)C)[(size_t)(row + 8) * N + col] = __floats2half2_rn(v10, v11);
            }
        }
    }
}

// ---------------------------------------------------------------------------
// Split QKV (fp16) + per-head LayerNorm on Q,K; copy V. fp16 head-major out.
// 8 lanes per row; 3-shuffle octet reduction.
// ---------------------------------------------------------------------------
__global__ __launch_bounds__(256) void qkv_split_ln8(
    const __half* __restrict__ qkv,
    const float* __restrict__ qg, const float* __restrict__ qb,
    const float* __restrict__ kg, const float* __restrict__ kb,
    __half* __restrict__ qh, __half* __restrict__ kh, __half* __restrict__ vh)
{
    const int oct = (blockIdx.x * blockDim.x + threadIdx.x) >> 3;
    const int l8  = threadIdx.x & 7;
    int t = oct / LN_ROWS_;
    int row = oct - t * LN_ROWS_;
    if (t >= 3) return;

    int b = row / (S_ * NH_);
    int rem = row - b * (S_ * NH_);
    int s = rem / NH_;
    int n = rem - s * NH_;

    const __half* src = qkv + (size_t)(b * S_ + s) * (3 * H_) + t * H_ + n * HD_ + l8 * 8;
    __half* dst = (t == 0 ? qh : (t == 1 ? kh : vh)) +
                  ((size_t)(b * NH_ + n) * S_ + s) * HD_ + l8 * 8;

    uint4 v = *(const uint4*)src;
    if (t == 2) { *(uint4*)dst = v; return; }

    __half2 hv[4];
    *(uint4*)hv = v;
    float x[8];
#pragma unroll
    for (int i = 0; i < 4; i++) {
        float2 f = __half22float2(hv[i]);
        x[2 * i] = f.x; x[2 * i + 1] = f.y;
    }

    float s1 = 0.f, s2 = 0.f;
#pragma unroll
    for (int i = 0; i < 8; i++) { s1 += x[i]; s2 += x[i] * x[i]; }
#pragma unroll
    for (int o = 1; o < 8; o <<= 1) {
        s1 += __shfl_xor_sync(0xffffffffu, s1, o);
        s2 += __shfl_xor_sync(0xffffffffu, s2, o);
    }
    float mu  = s1 * (1.0f / HD_);
    float var = s2 * (1.0f / HD_) - mu * mu;
    float inv = rsqrtf(var + 1e-5f);

    const float* g  = (t == 0) ? qg : kg;
    const float* be = (t == 0) ? qb : kb;
    float4 g0 = *(const float4*)&g[l8 * 8];
    float4 g1 = *(const float4*)&g[l8 * 8 + 4];
    float4 b0 = *(const float4*)&be[l8 * 8];
    float4 b1 = *(const float4*)&be[l8 * 8 + 4];

    __half2 oh[4];
    oh[0] = __floats2half2_rn((x[0] - mu) * inv * g0.x + b0.x,
                              (x[1] - mu) * inv * g0.y + b0.y);
    oh[1] = __floats2half2_rn((x[2] - mu) * inv * g0.z + b0.z,
                              (x[3] - mu) * inv * g0.w + b0.w);
    oh[2] = __floats2half2_rn((x[4] - mu) * inv * g1.x + b1.x,
                              (x[5] - mu) * inv * g1.y + b1.y);
    oh[3] = __floats2half2_rn((x[6] - mu) * inv * g1.z + b1.z,
                              (x[7] - mu) * inv * g1.w + b1.w);
    *(uint4*)dst = *(uint4*)oh;
}

// ---------------------------------------------------------------------------
// Causal flash attention, fp16 tensor cores; K/V double-buffered via cp.async.
// One cp_wait+__syncthreads per 32-key tile; prefetch overlaps compute.
// ---------------------------------------------------------------------------
#define QST 72
#define KST 72
#define VST 72

__global__ __launch_bounds__(256, 2) void flash_attn_fp16(
    const __half* __restrict__ qh, const __half* __restrict__ kh,
    const __half* __restrict__ vh, __half* __restrict__ ctx)
{
    __shared__ __half Qs[128][QST];
    __shared__ __half Ks[2][32][KST];
    __shared__ __half Vs[2][32][VST];

    const int bh  = blockIdx.y;
    const int qt  = blockIdx.x;
    const int tid = threadIdx.x;
    const int lane = tid & 31;
    const int w    = tid >> 5;
    const int gid  = lane >> 2;
    const int tig  = lane & 3;
    const int l8   = lane & 7;
    const int h8   = (lane >> 3) & 1;
    const int h16  = (lane >> 4) & 1;
    const int qbase = qt * 128;
    const int wrow  = w * 16;

    const __half* Q  = qh + (size_t)bh * S_ * HD_ + (size_t)qbase * HD_;
    const __half* Kp = kh + (size_t)bh * S_ * HD_;
    const __half* Vp = vh + (size_t)bh * S_ * HD_;

    // --- Stage Q + register-resident A fragments ---
    for (int i = tid; i < 128 * 8; i += 256) {
        int r = i >> 3, c8 = (i & 7) * 8;
        *(uint4*)&Qs[r][c8] = *(const uint4*)&Q[r * HD_ + c8];
    }
    __syncthreads();

    const uint32_t qsB = (uint32_t)__cvta_generic_to_shared(&Qs[0][0]) +
                         ((uint32_t)(wrow + l8 + h8 * 8) * QST + h16 * 8) * 2;
    uint32_t qa[4][4];
#pragma unroll
    for (int ks = 0; ks < 4; ks++)
        ldsm_x4(qa[ks], qsB + (uint32_t)(ks * 16) * 2);
    __syncthreads();

    const uint32_t ksS = (uint32_t)__cvta_generic_to_shared(&Ks[0][0][0]);
    const uint32_t vsS = (uint32_t)__cvta_generic_to_shared(&Vs[0][0][0]);
    const uint32_t KBUF = 32 * KST * 2;
    const uint32_t VBUF = 32 * VST * 2;
    const uint32_t ksOff = ((uint32_t)(l8 + h16 * 8) * KST + h8 * 8) * 2;
    const uint32_t vsOff = ((uint32_t)(l8 + h8 * 8) * VST + h16 * 8) * 2;
    // per-thread cp.async coords (one uint4 each for K and V)
    const int cr  = tid >> 3;           // 0..31
    const int cc8 = (tid & 7) * 8;      // half offset
    const uint32_t kSt = (uint32_t)(cr * KST + cc8) * 2;
    const uint32_t vSt = (uint32_t)(cr * VST + cc8) * 2;

    float o[8][4];
#pragma unroll
    for (int i = 0; i < 8; i++)
#pragma unroll
        for (int j = 0; j < 4; j++) o[i][j] = 0.f;
    float m0 = -CUDART_INF_F, m1 = -CUDART_INF_F;
    float l0 = 0.f, l1 = 0.f;

    const int r0g = qbase + wrow + gid;
    const int r1g = r0g + 8;
    const int rmaxw = qbase + wrow + 15;
    const int nkt = (qt + 1) * 4;
    const float scl = 0.125f;

    // prologue: prefetch tile 0
    cp16(ksS + kSt, &Kp[(size_t)cr * HD_ + cc8]);
    cp16(vsS + vSt, &Vp[(size_t)cr * HD_ + cc8]);
    cp_commit();

    for (int kt = 0; kt < nkt; kt++) {
        const int kbase = kt * 32;
        cp_wait<0>();        // tile kt resident (this thread's copies)
        __syncthreads();     // all visible; reads of tile kt-1 done

        if (kt + 1 < nkt) {  // prefetch tile kt+1 into other buffer
            const uint32_t nb = (uint32_t)((kt + 1) & 1);
            const size_t roff = (size_t)(kbase + 32 + cr) * HD_ + cc8;
            cp16(ksS + nb * KBUF + kSt, &Kp[roff]);
            cp16(vsS + nb * VBUF + vSt, &Vp[roff]);
            cp_commit();
        }

        if (kbase <= rmaxw) {
            const uint32_t buf = (uint32_t)(kt & 1);
            const uint32_t ksB = ksS + buf * KBUF + ksOff;
            const uint32_t vsB = vsS + buf * VBUF + vsOff;

            float s[4][4];
#pragma unroll
            for (int nt = 0; nt < 4; nt++)
#pragma unroll
                for (int j = 0; j < 4; j++) s[nt][j] = 0.f;
#pragma unroll
            for (int np = 0; np < 2; np++) {
#pragma unroll
                for (int ks = 0; ks < 4; ks++) {
                    uint32_t b4[4];
                    ldsm_x4(b4, ksB + (uint32_t)(np * 16 * KST + ks * 16) * 2);
                    mma_fp16(s[2 * np],     qa[ks], &b4[0]);
                    mma_fp16(s[2 * np + 1], qa[ks], &b4[2]);
                }
            }

            if (kbase + 31 <= qbase + wrow) {
#pragma unroll
                for (int nt = 0; nt < 4; nt++)
#pragma unroll
                    for (int j = 0; j < 4; j++) s[nt][j] *= scl;
            } else {
#pragma unroll
                for (int nt = 0; nt < 4; nt++) {
                    int c0 = kbase + nt * 8 + tig * 2;
                    s[nt][0] = (c0     <= r0g) ? s[nt][0] * scl : -CUDART_INF_F;
                    s[nt][1] = (c0 + 1 <= r0g) ? s[nt][1] * scl : -CUDART_INF_F;
                    s[nt][2] = (c0     <= r1g) ? s[nt][2] * scl : -CUDART_INF_F;
                    s[nt][3] = (c0 + 1 <= r1g) ? s[nt][3] * scl : -CUDART_INF_F;
                }
            }

            float mt0 = fmaxf(fmaxf(s[0][0], s[0][1]), fmaxf(s[1][0], s[1][1]));
            mt0 = fmaxf(mt0, fmaxf(fmaxf(s[2][0], s[2][1]), fmaxf(s[3][0], s[3][1])));
            float mt1 = fmaxf(fmaxf(s[0][2], s[0][3]), fmaxf(s[1][2], s[1][3]));
            mt1 = fmaxf(mt1, fmaxf(fmaxf(s[2][2], s[2][3]), fmaxf(s[3][2], s[3][3])));
            mt0 = fmaxf(mt0, __shfl_xor_sync(0xffffffffu, mt0, 1));
            mt0 = fmaxf(mt0, __shfl_xor_sync(0xffffffffu, mt0, 2));
            mt1 = fmaxf(mt1, __shfl_xor_sync(0xffffffffu, mt1, 1));
            mt1 = fmaxf(mt1, __shfl_xor_sync(0xffffffffu, mt1, 2));

            float mn0 = fmaxf(m0, mt0), mn1 = fmaxf(m1, mt1);
            float a0 = __expf(m0 - mn0), a1 = __expf(m1 - mn1);
            m0 = mn0; m1 = mn1;

            float p[4][4];
            float ps0 = 0.f, ps1 = 0.f;
#pragma unroll
            for (int nt = 0; nt < 4; nt++) {
                p[nt][0] = __expf(s[nt][0] - mn0);
                p[nt][1] = __expf(s[nt][1] - mn0);
                p[nt][2] = __expf(s[nt][2] - mn1);
                p[nt][3] = __expf(s[nt][3] - mn1);
                ps0 += p[nt][0] + p[nt][1];
                ps1 += p[nt][2] + p[nt][3];
            }
            ps0 += __shfl_xor_sync(0xffffffffu, ps0, 1);
            ps0 += __shfl_xor_sync(0xffffffffu, ps0, 2);
            ps1 += __shfl_xor_sync(0xffffffffu, ps1, 1);
            ps1 += __shfl_xor_sync(0xffffffffu, ps1, 2);
            l0 = l0 * a0 + ps0;
            l1 = l1 * a1 + ps1;

            uint32_t pa[2][4];
#pragma unroll
            for (int ks = 0; ks < 2; ks++) {
                pa[ks][0] = h2r(p[2 * ks][0],     p[2 * ks][1]);
                pa[ks][1] = h2r(p[2 * ks][2],     p[2 * ks][3]);
                pa[ks][2] = h2r(p[2 * ks + 1][0], p[2 * ks + 1][1]);
                pa[ks][3] = h2r(p[2 * ks + 1][2], p[2 * ks + 1][3]);
            }

#pragma unroll
            for (int nt = 0; nt < 8; nt++) {
                o[nt][0] *= a0; o[nt][1] *= a0;
                o[nt][2] *= a1; o[nt][3] *= a1;
            }
#pragma unroll
            for (int np = 0; np < 4; np++) {
#pragma unroll
                for (int ks = 0; ks < 2; ks++) {
                    uint32_t b4[4];
                    ldsm_x4_t(b4, vsB + (uint32_t)(ks * 16 * VST + np * 16) * 2);
                    mma_fp16(o[2 * np],     pa[ks], &b4[0]);
                    mma_fp16(o[2 * np + 1], pa[ks], &b4[2]);
                }
            }
        }
    }

    const int bb = bh >> 4;
    const int nh = bh & 15;
    const float inv0 = 1.0f / l0;
    const float inv1 = 1.0f / l1;
    __half* orow0 = ctx + (size_t)(bb * S_ + r0g) * H_ + nh * HD_;
    __half* orow1 = ctx + (size_t)(bb * S_ + r1g) * H_ + nh * HD_;
#pragma unroll
    for (int nt = 0; nt < 8; nt++) {
        int col = nt * 8 + tig * 2;
        *(__half2*)&orow0[col] = __floats2half2_rn(o[nt][0] * inv0, o[nt][1] * inv0);
        *(__half2*)&orow1[col] = __floats2half2_rn(o[nt][2] * inv1, o[nt][3] * inv1);
    }
}

// ---------------------------------------------------------------------------
extern "C" void kernel_launch(void* const* d_in, const int* in_sizes, int n_in,
                              void* d_out, int out_size)
{
    const float* hs = (const float*)d_in[0];
    const float* Wa = (const float*)d_in[1];
    const float* ba = (const float*)d_in[2];
    const float* Wp = (const float*)d_in[3];
    const float* bp = (const float*)d_in[4];
    const float* qg = (const float*)d_in[5];
    const float* qb = (const float*)d_in[6];
    const float* kg = (const float*)d_in[7];
    const float* kb = (const float*)d_in[8];
    float* out = (float*)d_out;

    __half *qkvh, *hsh, *wah, *wph, *qh, *kh, *vh, *ctxh;
    cudaGetSymbolAddress((void**)&qkvh, g_qkvh);
    cudaGetSymbolAddress((void**)&hsh, g_hsh);
    cudaGetSymbolAddress((void**)&wah, g_wah);
    cudaGetSymbolAddress((void**)&wph, g_wph);
    cudaGetSymbolAddress((void**)&qh,  g_qh);
    cudaGetSymbolAddress((void**)&kh,  g_kh);
    cudaGetSymbolAddress((void**)&vh,  g_vh);
    cudaGetSymbolAddress((void**)&ctxh, g_ctxh);

    // 0) fp32 -> fp16 input conversions (single launch)
    {
        int n4 = N4_HS + N4_WA + N4_WP;
        f2h_all<<<(n4 + 255) / 256, 256>>>(
            (const float4*)hs, (const float4*)Wa, (const float4*)Wp,
            (uint2*)hsh, (uint2*)wah, (uint2*)wph);
    }

    // 1) QKV GEMM (fp16 out): [4096,1024] @ [1024,3072] + bias
    gemm_fp16p<__half><<<dim3(3 * H_ / 128, MROWS_ / 128), 256>>>(
        hsh, wah, ba, qkvh, MROWS_, 3 * H_, H_);

    // 2) split + QK layernorm + V copy (8 lanes/row)
    {
        int threads_total = 3 * LN_ROWS_ * 8;
        qkv_split_ln8<<<threads_total / 256, 256>>>(qkvh, qg, qb, kg, kb, qh, kh, vh);
    }

    // 3) causal flash attention (fp16; K/V double-buffered cp.async)
    flash_attn_fp16<<<dim3(S_ / 128, B_ * NH_), 256>>>(qh, kh, vh, ctxh);

    // 4) output projection (fp32 out): [4096,1024] @ [1024,1024] + bias
    gemm_fp16p<float><<<dim3(H_ / 128, MROWS_ / 128), 256>>>(
        ctxh, wph, bp, out, MROWS_, H_, H_);
}